// round 11
// baseline (speedup 1.0000x reference)
#include <cuda_runtime.h>

#define NXC 512
#define NYC 512
#define PHW 3
#define PP 6                  // patch size
#define BB 128
#define SS 1024
#define BH 8                  // band height (rows)
#define BANDS_PER_IMG (NXC / BH)      // 64
#define NBANDS (BB * BANDS_PER_IMG)   // 8192
#define CAP 96                // max sources per band (mean ~26)
#define NBKT 8                // column buckets per band (64 cols each)
#define BCAP 48               // per-bucket list capacity (mean ~3.5)

__device__ __forceinline__ float inv_alpha() { return 1.0f / (1.41421356237309515f * 0.92f); }

__device__ int    g_cnt[NBANDS];              // zero at load; render re-zeroes its own bin
__device__ float2 g_src[NBANDS * CAP];

__global__ void bin_kernel(const float* __restrict__ z) {
    int gid = blockIdx.x * blockDim.x + threadIdx.x;
    if (gid >= BB * SS) return;
    int b = gid >> 10;
    int s = gid & (SS - 1);

    float x0 = __ldg(&z[b * 2 * SS + s]);
    float y0 = __ldg(&z[b * 2 * SS + SS + s]);

    int patchx = __float2int_rn(x0) - PHW;
    int patchy = __float2int_rn(y0) - PHW;
    if (patchx < 0 || patchx >= NXC - PP || patchy < 0 || patchy >= NYC - PP) return;

    int band0 = patchx >> 3;
    int band1 = (patchx + PP - 1) >> 3;
    for (int bd = band0; bd <= band1; ++bd) {
        int bin = b * BANDS_PER_IMG + bd;
        int pos = atomicAdd(&g_cnt[bin], 1);
        if (pos < CAP) g_src[bin * CAP + pos] = make_float2(x0, y0);
    }
}

__global__ __launch_bounds__(256, 6) void render_kernel(float* __restrict__ out) {
    __shared__ float s_lx[CAP * PP];
    __shared__ float s_ly[CAP * PP];
    __shared__ int   s_px[CAP];
    __shared__ int   s_py[CAP];
    __shared__ int   s_bcnt[NBKT];
    __shared__ unsigned char s_blist[NBKT][BCAP];
    __shared__ int   s_n;

    int bin = blockIdx.x;
    int b   = bin >> 6;                               // image
    int r0  = (bin & (BANDS_PER_IMG - 1)) << 3;       // first global row of band
    int tid = threadIdx.x;
    int wid = tid >> 5;
    int lane = tid & 31;

    if (tid == 0) {
        int n = g_cnt[bin];
        s_n = (n > CAP) ? CAP : n;
        g_cnt[bin] = 0;                               // restore for next graph replay
    }
    if (tid < NBKT) s_bcnt[tid] = 0;
    __syncthreads();

    int n = s_n;

    // per-source-per-axis profile setup: 2 threads per source.
    // The y-axis thread also buckets the source by column stripe.
    if (tid < 2 * n) {
        int sid = tid >> 1;
        int ax  = tid & 1;
        float2 xy = g_src[bin * CAP + sid];
        float u0 = ax ? xy.y : xy.x;
        int pu = __float2int_rn(u0) - PHW;
        float up = u0 - (float)pu;
        const float ia = inv_alpha();

        float e[PP + 1];
#pragma unroll
        for (int k = 0; k <= PP; k++)
            e[k] = erff(((float)k - 0.5f - up) * ia);

        if (ax == 0) {
            s_px[sid] = pu;
#pragma unroll
            for (int k = 0; k < PP; k++)
                s_lx[sid * PP + k] = 500.0f * (e[k + 1] - e[k]);  // i0*0.5 folded
        } else {
            s_py[sid] = pu;
#pragma unroll
            for (int k = 0; k < PP; k++)
                s_ly[sid * PP + k] = 0.5f * (e[k + 1] - e[k]);
            int b0 = pu >> 6;
            int b1 = (pu + PP - 1) >> 6;
            for (int bd = b0; bd <= b1; ++bd) {
                int pos = atomicAdd(&s_bcnt[bd], 1);
                if (pos < BCAP) s_blist[bd][pos] = (unsigned char)sid;
            }
        }
    }
    __syncthreads();

    // gather: warp w owns a 64-col stripe; lane l owns cols (64w + 2l, +1), all 8 rows
    int col0 = (wid << 6) + (lane << 1);              // global column of acc[.][0]
    float2 acc[BH];
#pragma unroll
    for (int r = 0; r < BH; ++r) acc[r] = make_float2(0.f, 0.f);

    int cnt = s_bcnt[wid];
    if (cnt > BCAP) cnt = BCAP;
    for (int k = 0; k < cnt; ++k) {
        int s  = s_blist[wid][k];
        int rl = s_px[s] - r0;                        // warp-uniform: local patch row in [-5,7]
        int py = s_py[s];
        int dc0 = col0 - py;
        float ly0 = ((unsigned)dc0 < (unsigned)PP) ? s_ly[s * PP + dc0] : 0.f;
        int dc1 = dc0 + 1;
        float ly1 = ((unsigned)dc1 < (unsigned)PP) ? s_ly[s * PP + dc1] : 0.f;
#pragma unroll
        for (int r = 0; r < BH; ++r) {
            int i = r - rl;                           // warp-uniform
            if ((unsigned)i < (unsigned)PP) {
                float lx = s_lx[s * PP + i];          // broadcast
                acc[r].x += lx * ly0;
                acc[r].y += lx * ly1;
            }
        }
    }

    // store: coalesced float2 (256 B per warp-row)
    float* base = out + (size_t)b * NXC * NYC + (size_t)r0 * NYC + col0;
#pragma unroll
    for (int r = 0; r < BH; ++r)
        *(float2*)(base + r * NYC) = acc[r];
}

extern "C" void kernel_launch(void* const* d_in, const int* in_sizes, int n_in,
                              void* d_out, int out_size) {
    const float* z = (const float*)d_in[0];
    float* out = (float*)d_out;

    bin_kernel<<<(BB * SS + 255) / 256, 256>>>(z);
    render_kernel<<<NBANDS, 256>>>(out);
}

// round 12
// speedup vs baseline: 1.4044x; 1.4044x over previous
#include <cuda_runtime.h>

#define NXC 512
#define NYC 512
#define PHW 3
#define PP 6                   // patch size
#define BB 128
#define SS 1024
#define BH 32                  // band height (rows)
#define BANDS_PER_IMG (NXC / BH)      // 16
#define NBANDS (BB * BANDS_PER_IMG)   // 2048
#define NT 512                 // threads per block
#define CAP 192                // max sources per band (mean ~75)
#define NBKT 16                // 32-col stripes
#define BCAP 32                // per-bucket capacity (mean ~5.5)

__device__ __forceinline__ float inv_alpha() { return 1.0f / (1.41421356237309515f * 0.92f); }

__global__ __launch_bounds__(NT, 2) void render_kernel(const float* __restrict__ z,
                                                       float* __restrict__ out) {
    __shared__ float2 s_src[CAP];
    __shared__ float  s_lx[CAP * PP];
    __shared__ float  s_ly[CAP * PP];
    __shared__ int    s_px[CAP];
    __shared__ int    s_py[CAP];
    __shared__ int    s_bcnt[NBKT];
    __shared__ unsigned char s_blist[NBKT][BCAP];
    __shared__ int    s_n;

    int blk = blockIdx.x;
    int b   = blk >> 4;                               // image
    int r0  = (blk & (BANDS_PER_IMG - 1)) << 5;       // first global row of band
    int tid = threadIdx.x;
    int wid = tid >> 5;
    int lane = tid & 31;

    if (tid == 0) s_n = 0;
    if (tid < NBKT) s_bcnt[tid] = 0;
    __syncthreads();

    // 1) read this image's sources directly (coalesced), filter for band intersection
    {
        const float* zx = z + (size_t)b * 2 * SS;
#pragma unroll
        for (int k = 0; k < SS / NT; ++k) {
            int s = tid + k * NT;
            float x0 = __ldg(&zx[s]);
            float y0 = __ldg(&zx[SS + s]);
            int patchx = __float2int_rn(x0) - PHW;
            int patchy = __float2int_rn(y0) - PHW;
            bool valid = (patchx >= 0) & (patchx < NXC - PP) &
                         (patchy >= 0) & (patchy < NYC - PP);
            bool hit = valid & (patchx >= r0 - (PP - 1)) & (patchx < r0 + BH);
            if (hit) {
                int pos = atomicAdd(&s_n, 1);
                if (pos < CAP) s_src[pos] = make_float2(x0, y0);
            }
        }
    }
    __syncthreads();

    int n = s_n;
    if (n > CAP) n = CAP;

    // 2) per-source-per-axis profile setup: 2 threads per source.
    //    The y-axis thread also buckets the source by 32-col stripe.
    if (tid < 2 * n) {
        int sid = tid >> 1;
        int ax  = tid & 1;
        float2 xy = s_src[sid];
        float u0 = ax ? xy.y : xy.x;
        int pu = __float2int_rn(u0) - PHW;
        float up = u0 - (float)pu;
        const float ia = inv_alpha();

        float e[PP + 1];
#pragma unroll
        for (int k = 0; k <= PP; k++)
            e[k] = erff(((float)k - 0.5f - up) * ia);

        if (ax == 0) {
            s_px[sid] = pu;
#pragma unroll
            for (int k = 0; k < PP; k++)
                s_lx[sid * PP + k] = 500.0f * (e[k + 1] - e[k]);  // i0*0.5 folded
        } else {
            s_py[sid] = pu;
#pragma unroll
            for (int k = 0; k < PP; k++)
                s_ly[sid * PP + k] = 0.5f * (e[k + 1] - e[k]);
            int b0 = pu >> 5;
            int b1 = (pu + PP - 1) >> 5;
            for (int bd = b0; bd <= b1; ++bd) {
                int pos = atomicAdd(&s_bcnt[bd], 1);
                if (pos < BCAP) s_blist[bd][pos] = (unsigned char)sid;
            }
        }
    }
    __syncthreads();

    // 3) gather: warp w owns cols [32w, 32w+31]; lane owns 1 col, all 32 rows in regs
    int col = (wid << 5) + lane;
    float acc[BH];
#pragma unroll
    for (int r = 0; r < BH; ++r) acc[r] = 0.f;

    int cnt = s_bcnt[wid];
    if (cnt > BCAP) cnt = BCAP;
    for (int k = 0; k < cnt; ++k) {
        int s  = s_blist[wid][k];
        int rl = s_px[s] - r0;                        // warp-uniform, in [-5, 31]
        int dc = col - s_py[s];
        float ly = ((unsigned)dc < (unsigned)PP) ? s_ly[s * PP + dc] : 0.f;
#pragma unroll
        for (int r = 0; r < BH; ++r) {
            int i = r - rl;                           // warp-uniform predicate
            if ((unsigned)i < (unsigned)PP)
                acc[r] += s_lx[s * PP + i] * ly;      // broadcast LDS + FFMA
        }
    }

    // 4) store: coalesced (128 B per warp-row)
    float* base = out + (size_t)b * NXC * NYC + (size_t)r0 * NYC + col;
#pragma unroll
    for (int r = 0; r < BH; ++r)
        base[r * NYC] = acc[r];
}

extern "C" void kernel_launch(void* const* d_in, const int* in_sizes, int n_in,
                              void* d_out, int out_size) {
    const float* z = (const float*)d_in[0];
    float* out = (float*)d_out;
    render_kernel<<<NBANDS, NT>>>(z, out);
}